// round 10
// baseline (speedup 1.0000x reference)
#include <cuda_runtime.h>
#include <math.h>

#define HEIGHT 1024
#define WIDTH  2048
#define PPT 8      // pixels per thread = 4 packed f32x2 pairs
#define TPB 256

typedef unsigned long long ull;

// ---- f32x2 packed helpers (sm_103a FFMA2 path; PTX-only per SASS_QUICKREF) ----
__device__ __forceinline__ ull pk2(float lo, float hi) {
    ull r; asm("mov.b64 %0, {%1,%2};" : "=l"(r) : "f"(lo), "f"(hi)); return r;
}
__device__ __forceinline__ void upk2(float& lo, float& hi, ull v) {
    asm("mov.b64 {%0,%1}, %2;" : "=f"(lo), "=f"(hi) : "l"(v));
}
__device__ __forceinline__ ull fma2(ull a, ull b, ull c) {
    ull d; asm("fma.rn.f32x2 %0, %1, %2, %3;" : "=l"(d) : "l"(a), "l"(b), "l"(c)); return d;
}
__device__ __forceinline__ ull mul2(ull a, ull b) {
    ull d; asm("mul.rn.f32x2 %0, %1, %2;" : "=l"(d) : "l"(a), "l"(b)); return d;
}

// Grid trig tables, filled each call by init kernel (deterministic).
__device__ float g_sth[HEIGHT];
__device__ float g_cth[HEIGHT];
__device__ float g_sph[WIDTH];
__device__ float g_cph[WIDTH];

// Replicate the reference grid EXACTLY at float32 granularity (unchanged from
// the passing R7-R9 kernels -- keeps atan2 branch-cut flips at zero):
__global__ void init_tables_kernel()
{
    const int i = blockIdx.x * blockDim.x + threadIdx.x;
    if (i < HEIGHT) {
        const float gx = -1.0f + (float)i * (2.0f / (float)HEIGHT); // exact
        const float th = __fadd_rn(__fmul_rn(gx, 1.5707963267948966f),
                                   1.5707963267948966f);
        double s, c;
        sincos((double)th, &s, &c);
        g_sth[i] = (float)s;
        g_cth[i] = (float)c;
    } else if (i < HEIGHT + WIDTH) {
        const int j = i - HEIGHT;
        const float gy = -1.0f + (float)j * (2.0f / (float)WIDTH);  // exact
        const float ph = __fmul_rn(gy, 3.14159265358979323846f);
        double s, c;
        sincos((double)ph, &s, &c);
        g_sph[j] = (float)s;
        g_cph[j] = (float)c;
    }
}

__global__ void __launch_bounds__(TPB)
depth3dgrid_kernel(const float* __restrict__ depth,
                   const float* __restrict__ trans,
                   float* __restrict__ out)
{
    __shared__ float sT[16];
    const int b = blockIdx.y;
    if (threadIdx.x < 16) sT[threadIdx.x] = trans[b * 16 + threadIdx.x];
    __syncthreads();

    // 8 consecutive pixels, same row (8 | 2048)
    const int base = (blockIdx.x * TPB + threadIdx.x) * PPT;
    const int h  = base >> 11;          // / WIDTH
    const int w0 = base & (WIDTH - 1);  // % WIDTH

    const float s_th = g_sth[h];
    const float c_th = g_cth[h];

    // Row-constant hoist (same scalar values as R9), broadcast into f32x2 lanes
    const ull A0 = pk2(s_th * sT[0], s_th * sT[0]);
    const ull A1 = pk2(s_th * sT[1], s_th * sT[1]);
    const ull A2 = pk2(s_th * sT[2], s_th * sT[2]);
    const ull B0 = pk2(s_th * sT[4], s_th * sT[4]);
    const ull B1 = pk2(s_th * sT[5], s_th * sT[5]);
    const ull B2 = pk2(s_th * sT[6], s_th * sT[6]);
    const ull K0 = pk2(c_th * sT[8],  c_th * sT[8]);
    const ull K1 = pk2(c_th * sT[9],  c_th * sT[9]);
    const ull K2 = pk2(c_th * sT[10], c_th * sT[10]);
    const ull T30 = pk2(sT[12], sT[12]);
    const ull T31 = pk2(sT[13], sT[13]);
    const ull T32 = pk2(sT[14], sT[14]);

    // broadcast constants
    const ull TINY  = pk2(1e-30f, 1e-30f);
    const ull MEPS  = pk2(-1e-4f, -1e-4f);
    const ull ONE   = pk2(1.0f, 1.0f);
    const ull M1    = pk2(-1.0f, -1.0f);
    const ull C2PI  = pk2(0.6366197723675814f, 0.6366197723675814f);
    // acos P3 coeffs (A&S 4.4.45)
    const ull CA3 = pk2(-0.0187293f, -0.0187293f);
    const ull CA2 = pk2( 0.0742610f,  0.0742610f);
    const ull CA1 = pk2(-0.2121144f, -0.2121144f);
    const ull CA0 = pk2( 1.5707288f,  1.5707288f);
    // atan P9 coeffs
    const ull CB4 = pk2( 0.0208351f,  0.0208351f);
    const ull CB3 = pk2(-0.0851330f, -0.0851330f);
    const ull CB2 = pk2( 0.1801410f,  0.1801410f);
    const ull CB1 = pk2(-0.3302995f, -0.3302995f);
    const ull CB0 = pk2( 0.9998660f,  0.9998660f);

    // 128-bit loads: tables/depth are contiguous -> pre-packed f32x2 pairs
    const ulonglong2* cpp = (const ulonglong2*)(g_cph + w0);
    const ulonglong2* spp = (const ulonglong2*)(g_sph + w0);
    const ulonglong2* dpp = (const ulonglong2*)(depth + (size_t)b * (HEIGHT * WIDTH) + base);
    const ulonglong2 cpa = cpp[0], cpb = cpp[1];
    const ulonglong2 spa = spp[0], spb = spp[1];
    const ulonglong2 dva = dpp[0], dvb = dpp[1];
    const ull CPs[4] = {cpa.x, cpa.y, cpb.x, cpb.y};
    const ull SPs[4] = {spa.x, spa.y, spb.x, spb.y};
    const ull DDs[4] = {dva.x, dva.y, dvb.x, dvb.y};

    const float PI     = 3.14159265358979323846f;
    const float HALFPI = 1.5707963267948966f;
    const float INVPI  = 0.3183098861837907f;

    float res[16];
#pragma unroll
    for (int j = 0; j < 4; ++j) {
        const ull CP = CPs[j], SP = SPs[j], D = DDs[j];

        // transform (IEEE-RN packed fma == scalar fmaf chain of R9, bit-identical)
        const ull PX = fma2(D, fma2(CP, A0, fma2(SP, B0, K0)), T30);
        const ull PY = fma2(D, fma2(CP, A1, fma2(SP, B1, K1)), T31);
        const ull PZ = fma2(D, fma2(CP, A2, fma2(SP, B2, K2)), T32);

        // s2 with tiny bias folded into innermost fma (rsqrt(0) guard)
        const ull S2 = fma2(PX, PX, fma2(PY, PY, fma2(PZ, PZ, TINY)));
        float s20, s21; upk2(s20, s21, S2);
        const ull RIS = pk2(rsqrtf(s20), rsqrtf(s21));

        // t = pz*ris*(1 - 1e-4*ris)  (first-order 1/(sqrt+eps))
        const ull PR = mul2(PZ, RIS);
        const ull T  = fma2(mul2(PR, RIS), MEPS, PR);

        // acos(|t|) = sqrt(1-|t|) * P3(|t|), packed
        const ull XA = T & 0x7FFFFFFF7FFFFFFFULL;
        ull P = fma2(XA, CA3, CA2);
        P = fma2(P, XA, CA1);
        P = fma2(P, XA, CA0);
        const ull U = fma2(XA, M1, ONE);
        float u0, u1; upk2(u0, u1, U);
        u0 = fmaxf(u0, 1e-30f); u1 = fmaxf(u1, 1e-30f);
        const ull SQ = mul2(pk2(u0, u1), pk2(rsqrtf(u0), rsqrtf(u1))); // sqrt(u)
        const ull AC = mul2(P, SQ);
        const ull V  = fma2(AC, C2PI, M1);    // acos(|t|)*2/pi - 1  (<= 0)

        float t0, t1; upk2(t0, t1, T);
        float v0, v1; upk2(v0, v1, V);
        const float theta0 = (t0 >= 0.0f) ? v0 : -v0;  // == (PI-ac) branch of R9
        const float theta1 = (t1 >= 0.0f) ? v1 : -v1;

        // atan2(py, px): packed P9 poly, scalar quadrant fixes (R9-identical)
        float px0, px1, py0, py1;
        upk2(px0, px1, PX); upk2(py0, py1, PY);
        const float ax0 = fabsf(px0), ay0 = fabsf(py0);
        const float ax1 = fabsf(px1), ay1 = fabsf(py1);
        const float mx0 = fmaxf(ax0, ay0), mn0 = fminf(ax0, ay0);
        const float mx1 = fmaxf(ax1, ay1), mn1 = fminf(ax1, ay1);
        const ull Aq = pk2(__fdividef(mn0, mx0), __fdividef(mn1, mx1));
        const ull SS = mul2(Aq, Aq);
        ull Q = fma2(SS, CB4, CB3);
        Q = fma2(Q, SS, CB2);
        Q = fma2(Q, SS, CB1);
        Q = fma2(Q, SS, CB0);
        Q = mul2(Q, Aq);
        float q0, q1; upk2(q0, q1, Q);
        q0 = (ay0 > ax0)   ? (HALFPI - q0) : q0;
        q1 = (ay1 > ax1)   ? (HALFPI - q1) : q1;
        q0 = (px0 < 0.0f)  ? (PI - q0)     : q0;
        q1 = (px1 < 0.0f)  ? (PI - q1)     : q1;
        const float phi0 = copysignf(q0, py0) * INVPI;
        const float phi1 = copysignf(q1, py1) * INVPI;

        res[4 * j + 0] = phi0;   res[4 * j + 1] = theta0;
        res[4 * j + 2] = phi1;   res[4 * j + 3] = theta1;
    }

    float4* optr = (float4*)(out + ((size_t)b * (HEIGHT * WIDTH) + base) * 2);
#pragma unroll
    for (int i = 0; i < 4; ++i)
        optr[i] = make_float4(res[4 * i], res[4 * i + 1],
                              res[4 * i + 2], res[4 * i + 3]);
}

extern "C" void kernel_launch(void* const* d_in, const int* in_sizes, int n_in,
                              void* d_out, int out_size)
{
    const float* depth = (const float*)d_in[0];   // (4,1024,2048,1) f32
    const float* trans = (const float*)d_in[1];   // (4,4,4) f32
    float* out = (float*)d_out;                   // (4,1024,2048,2) f32

    init_tables_kernel<<<(HEIGHT + WIDTH + 127) / 128, 128>>>();

    dim3 grid(HEIGHT * WIDTH / (TPB * PPT), 4, 1); // (1024, 4)
    depth3dgrid_kernel<<<grid, TPB>>>(depth, trans, out);
}

// round 11
// speedup vs baseline: 1.1710x; 1.1710x over previous
#include <cuda_runtime.h>
#include <math.h>

#define HEIGHT 1024
#define WIDTH  2048
#define PPT 8      // pixels per thread, scalar (8 | 2048, float4 aligned)
#define TPB 256

// Grid trig tables, filled each call by init kernel (deterministic).
__device__ float g_sth[HEIGHT];
__device__ float g_cth[HEIGHT];
__device__ float g_sph[WIDTH];
__device__ float g_cph[WIDTH];

// Replicate the reference grid EXACTLY at float32 granularity (unchanged from
// the passing R7-R9 kernels -- keeps atan2 branch-cut flips at zero):
//   theta = fl32( fl32(gx * fl32(pi/2)) + fl32(pi/2) ),  gx exact
//   phi   = fl32( gy * fl32(pi) ),                       gy exact
// sin/cos in double, rounded to float (<=1 ulp vs numpy float32).
__global__ void init_tables_kernel()
{
    const int i = blockIdx.x * blockDim.x + threadIdx.x;
    if (i < HEIGHT) {
        const float gx = -1.0f + (float)i * (2.0f / (float)HEIGHT);
        const float th = __fadd_rn(__fmul_rn(gx, 1.5707963267948966f),
                                   1.5707963267948966f);
        double s, c;
        sincos((double)th, &s, &c);
        g_sth[i] = (float)s;
        g_cth[i] = (float)c;
    } else if (i < HEIGHT + WIDTH) {
        const int j = i - HEIGHT;
        const float gy = -1.0f + (float)j * (2.0f / (float)WIDTH);
        const float ph = __fmul_rn(gy, 3.14159265358979323846f);
        double s, c;
        sincos((double)ph, &s, &c);
        g_sph[j] = (float)s;
        g_cph[j] = (float)c;
    }
}

__device__ __forceinline__ float fsqrt_approx(float x) {
    float r;
    asm("sqrt.approx.f32 %0, %1;" : "=f"(r) : "f"(x));
    return r;
}

__global__ void __launch_bounds__(TPB)
depth3dgrid_kernel(const float* __restrict__ depth,
                   const float* __restrict__ trans,
                   float* __restrict__ out)
{
    __shared__ float sT[16];
    const int b = blockIdx.y;
    if (threadIdx.x < 16) sT[threadIdx.x] = trans[b * 16 + threadIdx.x];
    __syncthreads();

    // 8 consecutive pixels, same row (8 | 2048)
    const int base = (blockIdx.x * TPB + threadIdx.x) * PPT;
    const int h  = base >> 11;          // / WIDTH
    const int w0 = base & (WIDTH - 1);  // % WIDTH

    const float s_th = g_sth[h];
    const float c_th = g_cth[h];

    // Row-constant hoist (identical values to R9): amortized over 8 px now
    const float a0 = s_th * sT[0],  a1 = s_th * sT[1],  a2 = s_th * sT[2];
    const float b0 = s_th * sT[4],  b1 = s_th * sT[5],  b2 = s_th * sT[6];
    const float k0 = c_th * sT[8],  k1 = c_th * sT[9],  k2 = c_th * sT[10];
    const float T30 = sT[12], T31 = sT[13], T32 = sT[14];

    // 128-bit loads of tables + depth (contiguous, aligned)
    const float4* cpp = (const float4*)(g_cph + w0);
    const float4* spp = (const float4*)(g_sph + w0);
    const float4* dpp = (const float4*)(depth + (size_t)b * (HEIGHT * WIDTH) + base);
    const float4 cp0 = cpp[0], cp1 = cpp[1];
    const float4 sp0 = spp[0], sp1 = spp[1];
    const float4 dv0 = dpp[0], dv1 = dpp[1];
    const float cpa[8] = {cp0.x, cp0.y, cp0.z, cp0.w, cp1.x, cp1.y, cp1.z, cp1.w};
    const float spa[8] = {sp0.x, sp0.y, sp0.z, sp0.w, sp1.x, sp1.y, sp1.z, sp1.w};
    const float dd[8]  = {dv0.x, dv0.y, dv0.z, dv0.w, dv1.x, dv1.y, dv1.z, dv1.w};

    const float PI     = 3.14159265358979323846f;
    const float HALFPI = 1.5707963267948966f;
    const float INVPI  = 0.3183098861837907f;

    float4* optr = (float4*)(out + ((size_t)b * (HEIGHT * WIDTH) + base) * 2);

    // Process pixel pairs; store one float4 per pair to cap live registers.
#pragma unroll
    for (int j = 0; j < 4; ++j) {
        float ph_o[2], th_o[2];
#pragma unroll
        for (int e = 0; e < 2; ++e) {
            const int k = 2 * j + e;
            const float cp = cpa[k], sp = spa[k], d = dd[k];

            // transform (bit-identical fma chain to R9 -- sign-critical)
            const float px = fmaf(d, fmaf(cp, a0, fmaf(sp, b0, k0)), T30);
            const float py = fmaf(d, fmaf(cp, a1, fmaf(sp, b1, k1)), T31);
            const float pz = fmaf(d, fmaf(cp, a2, fmaf(sp, b2, k2)), T32);

            // t = pz / (sqrt(s2) + 1e-4) via rsqrt + first-order expansion
            const float s2  = fmaf(px, px, fmaf(py, py, fmaf(pz, pz, 1e-30f)));
            const float ris = rsqrtf(s2);
            const float pr  = pz * ris;
            const float t   = fmaf(pr * ris, -1e-4f, pr);

            // acos(|t|) = sqrt(1-|t|) * P3(|t|)  (A&S 4.4.45)
            const float xa = fabsf(t);
            float p = fmaf(xa, -0.0187293f, 0.0742610f);
            p = fmaf(p, xa, -0.2121144f);
            p = fmaf(p, xa,  1.5707288f);
            const float u  = fmaxf(1.0f - xa, 1e-30f);
            const float ac = p * fsqrt_approx(u);         // acos(|t|)
            const float v  = fmaf(ac, 0.6366197723675814f, -1.0f); // <= 0
            // theta = +v if t>=0 else -v  (sign-bit XOR; exact incl. t = -0)
            th_o[e] = __int_as_float(__float_as_int(v) ^
                                     (__float_as_int(t) & 0x80000000));

            // atan2(py, px): degree-9 odd minimax + quadrant fixes (R9-identical)
            const float ax = fabsf(px), ay = fabsf(py);
            const float mx = fmaxf(fmaxf(ax, ay), 1e-37f);
            const float mn = fminf(ax, ay);
            const float a  = __fdividef(mn, mx);
            const float ss = a * a;
            float q = fmaf(ss, 0.0208351f, -0.0851330f);
            q = fmaf(q, ss,  0.1801410f);
            q = fmaf(q, ss, -0.3302995f);
            q = fmaf(q, ss,  0.9998660f);
            q = q * a;                                   // atan(mn/mx)
            q = (ay > ax)   ? (HALFPI - q) : q;
            q = (px < 0.0f) ? (PI - q)     : q;
            ph_o[e] = copysignf(q, py) * INVPI;
        }
        optr[j] = make_float4(ph_o[0], th_o[0], ph_o[1], th_o[1]);
    }
}

extern "C" void kernel_launch(void* const* d_in, const int* in_sizes, int n_in,
                              void* d_out, int out_size)
{
    const float* depth = (const float*)d_in[0];   // (4,1024,2048,1) f32
    const float* trans = (const float*)d_in[1];   // (4,4,4) f32
    float* out = (float*)d_out;                   // (4,1024,2048,2) f32

    init_tables_kernel<<<(HEIGHT + WIDTH + 127) / 128, 128>>>();

    dim3 grid(HEIGHT * WIDTH / (TPB * PPT), 4, 1); // (1024, 4)
    depth3dgrid_kernel<<<grid, TPB>>>(depth, trans, out);
}